// round 1
// baseline (speedup 1.0000x reference)
#include <cuda_runtime.h>
#include <cuda_bf16.h>

// DWTModelFullBand: the reference applies a 2-level Haar DWT and then exactly
// inverts it (idwt2 is the algebraic inverse of dwt2; the stack/reshape is an
// identity permutation). The whole pipeline is x_rec == x up to a few ulps of
// fp32 rounding (~1e-6 abs), far under the 1e-3 rel-err gate. The optimal
// kernel is a pure HBM-bound 96 MB copy.

__global__ void __launch_bounds__(256)
dwt_identity_copy_kernel(const float4* __restrict__ in,
                         float4* __restrict__ out,
                         int n_vec4) {
    int i = blockIdx.x * blockDim.x + threadIdx.x;
    if (i < n_vec4) {
        out[i] = in[i];
    }
}

extern "C" void kernel_launch(void* const* d_in, const int* in_sizes, int n_in,
                              void* d_out, int out_size) {
    const float4* x = (const float4*)d_in[0];
    float4* out = (float4*)d_out;

    // out_size = 32*3*512*512 = 25,165,824 floats, divisible by 4.
    int n_vec4 = out_size / 4;            // 6,291,456
    int threads = 256;
    int blocks = (n_vec4 + threads - 1) / threads;  // 24,576

    dwt_identity_copy_kernel<<<blocks, threads>>>(x, out, n_vec4);
}